// round 6
// baseline (speedup 1.0000x reference)
#include <cuda_runtime.h>
#include <cstdint>

// SigJoin (Chen's identity), D=8, M=6, BATCH=128, SIGLEN=299592.
// z_k[j] = x_k[j] + A(j>>3)*y[j&7].  Hierarchical factoring:
//   A(8q+d) = x_{K-1}[8q+d] + ys[d] * C(q)
//   C(q)    = sum_{i=1}^{K-2} x_i[q>>3(K-2-i)] * P'_i * invf(K-i) + P' * invf(K)
// One thread per aligned 64-element super-group: C once, 8 prefix floats
// (2x coalesced float4), then 8 streamed float4-pairs in/out.

#define SJ_D      8
#define SJ_SIGLEN 299592
#define SJ_BATCH  128
#define SJ_SG     4681          // super-groups per row (levels 2..6)

__device__ __forceinline__ float sj_invf(int n) {
    const float t[7] = {0.f, 1.f, 0.5f, 1.f/6.f, 1.f/24.f, 1.f/120.f, 1.f/720.f};
    return t[n];
}

__device__ __forceinline__ int sj_loff(int i) {
    const int t[7] = {0, 0, 8, 72, 584, 4680, 37448};
    return t[i];
}

// C(q) for level K (K>=2). Loop i = K-2 .. 1 folds digits of q.
template <int K>
__device__ __forceinline__ float sj_chenB(const float* __restrict__ xr,
                                          const float* __restrict__ ys,
                                          int q) {
    float C = 0.f;
    float P = 1.f;
    int idx = q;
#pragma unroll
    for (int i = K - 2; i >= 1; --i) {
        C += __ldg(xr + sj_loff(i) + idx) * (P * sj_invf(K - i));
        P *= ys[idx & 7];
        idx >>= 3;
    }
    return C + P * sj_invf(K);
}

__global__ __launch_bounds__(256) void sigjoin64_kernel(
    const float* __restrict__ x,   // [BATCH, SIGLEN]
    const float* __restrict__ y,   // [BATCH, 8]
    float* __restrict__ out)       // [BATCH, SIGLEN]
{
    const int b = blockIdx.y;
    __shared__ float ys[8];
    if (threadIdx.x < 8) ys[threadIdx.x] = y[b * SJ_D + threadIdx.x];
    __syncthreads();

    const float* xr   = x   + (size_t)b * SJ_SIGLEN;
    float*       orow = out + (size_t)b * SJ_SIGLEN;

    // Level 1 (8 elements): z = x + y. Done by 8 threads of block 0.
    if (blockIdx.x == 0 && threadIdx.x < 8)
        orow[threadIdx.x] = xr[threadIdx.x] + ys[threadIdx.x];

    const int u = blockIdx.x * blockDim.x + threadIdx.x;  // super-group id
    if (u >= SJ_SG) return;

    // Dispatch: level K, level-local super index q, column base c,
    // prefix base pK = loff(K-1) + 8q.
    int c, q, pK;
    float C;
    if (u >= 585)      { q = u - 585; c = 37448 + q * 64; C = sj_chenB<6>(xr, ys, q); pK = 4680 + 8 * q; }
    else if (u >= 73)  { q = u - 73;  c = 4680  + q * 64; C = sj_chenB<5>(xr, ys, q); pK = 584  + 8 * q; }
    else if (u >= 9)   { q = u - 9;   c = 584   + q * 64; C = sj_chenB<4>(xr, ys, q); pK = 72   + 8 * q; }
    else if (u >= 1)   { q = u - 1;   c = 72    + q * 64; C = sj_chenB<3>(xr, ys, q); pK = 8    + 8 * q; }
    else               { q = 0;       c = 8;              C = 0.5f;                    pK = 0;           }

    // Prefix values x_{K-1}[8q .. 8q+7]: two coalesced float4 loads (cached).
    const float4 xpa = __ldg(reinterpret_cast<const float4*>(xr + pK));
    const float4 xpb = __ldg(reinterpret_cast<const float4*>(xr + pK + 4));
    const float xp[8] = {xpa.x, xpa.y, xpa.z, xpa.w, xpb.x, xpb.y, xpb.z, xpb.w};

    float A[8];
#pragma unroll
    for (int d = 0; d < 8; ++d) A[d] = fmaf(ys[d], C, xp[d]);

    // Stream 64 elements: 8 sub-groups of 8 (2x float4 each).
#pragma unroll
    for (int d = 0; d < 8; ++d) {
        const int cc = c + 8 * d;
        const float4 x0 = __ldcs(reinterpret_cast<const float4*>(xr + cc));
        const float4 x1 = __ldcs(reinterpret_cast<const float4*>(xr + cc + 4));
        float4 z0, z1;
        z0.x = fmaf(A[d], ys[0], x0.x);
        z0.y = fmaf(A[d], ys[1], x0.y);
        z0.z = fmaf(A[d], ys[2], x0.z);
        z0.w = fmaf(A[d], ys[3], x0.w);
        z1.x = fmaf(A[d], ys[4], x1.x);
        z1.y = fmaf(A[d], ys[5], x1.y);
        z1.z = fmaf(A[d], ys[6], x1.z);
        z1.w = fmaf(A[d], ys[7], x1.w);
        __stcs(reinterpret_cast<float4*>(orow + cc),     z0);
        __stcs(reinterpret_cast<float4*>(orow + cc + 4), z1);
    }
}

extern "C" void kernel_launch(void* const* d_in, const int* in_sizes, int n_in,
                              void* d_out, int out_size) {
    const float* x = (const float*)d_in[0];   // [128, 299592] fp32
    const float* y = (const float*)d_in[1];   // [128, 8] fp32
    float* out = (float*)d_out;

    dim3 block(256);
    dim3 grid((SJ_SG + 255) / 256, SJ_BATCH);   // 19 x 128
    sigjoin64_kernel<<<grid, block>>>(x, y, out);
}

// round 8
// speedup vs baseline: 1.8091x; 1.8091x over previous
#include <cuda_runtime.h>
#include <cstdint>

// SigJoin (Chen's identity), D=8, M=6, BATCH=128, SIGLEN=299592.
// z[j] = x[j] + A(j>>3) * y[j&7];  A per aligned 8-group.
// Coalesced mapping: thread handles groups u and u+HALF (both contiguous
// streams across the warp). y kept in registers for the fixed-index FMAs;
// smem ys[] only for the dynamic digit lookups in the prefix accumulator.

#define SJ_D      8
#define SJ_SIGLEN 299592
#define SJ_BATCH  128
#define SJ_GROUPS 37449          // SIGLEN / 8
#define SJ_HALF   18725          // ceil(GROUPS / 2)

__device__ __forceinline__ float sj_invf(int n) {
    const float t[7] = {0.f, 1.f, 0.5f, 1.f/6.f, 1.f/24.f, 1.f/120.f, 1.f/720.f};
    return t[n];
}

__device__ __forceinline__ int sj_loff(int i) {
    const int t[7] = {0, 0, 8, 72, 584, 4680, 37448};
    return t[i];
}

// A = sum_{i=0}^{K-1} X_i * P_i * invf(K-i),  P_i = prod_{t=i}^{K-2} y[d_t].
template <int K>
__device__ __forceinline__ float sj_chenA(const float* __restrict__ xr,
                                          const float* __restrict__ ys,
                                          int r) {
    float A = 0.f;
    float P = 1.f;
    int idx = r;
#pragma unroll
    for (int i = K - 1; i >= 1; --i) {
        idx >>= 3;
        A += __ldg(xr + sj_loff(i) + idx) * (P * sj_invf(K - i));
        P *= ys[idx & 7];
    }
    return A + P * sj_invf(K);
}

__device__ __forceinline__ float sj_dispatchA(const float* __restrict__ xr,
                                              const float* __restrict__ ys,
                                              int c) {
    if (c >= 37448)     return sj_chenA<6>(xr, ys, c - 37448);
    else if (c >= 4680) return sj_chenA<5>(xr, ys, c - 4680);
    else if (c >= 584)  return sj_chenA<4>(xr, ys, c - 584);
    else if (c >= 72)   return sj_chenA<3>(xr, ys, c - 72);
    else if (c >= 8)    return sj_chenA<2>(xr, ys, c - 8);
    else                return 1.f;          // level 1: z = x + y
}

__global__ __launch_bounds__(256) void sigjoin2g_kernel(
    const float* __restrict__ x,   // [BATCH, SIGLEN]
    const float* __restrict__ y,   // [BATCH, 8]
    float* __restrict__ out)       // [BATCH, SIGLEN]
{
    const int b = blockIdx.y;
    __shared__ float ys[8];
    if (threadIdx.x < 8) ys[threadIdx.x] = y[b * SJ_D + threadIdx.x];
    __syncthreads();

    // Register-resident y for fixed-index FMAs (broadcast L1 hit).
    const float4 ya = __ldg(reinterpret_cast<const float4*>(y + b * SJ_D));
    const float4 yb = __ldg(reinterpret_cast<const float4*>(y + b * SJ_D + 4));

    const int u = blockIdx.x * blockDim.x + threadIdx.x;
    if (u >= SJ_HALF) return;

    const float* xr   = x   + (size_t)b * SJ_SIGLEN;
    float*       orow = out + (size_t)b * SJ_SIGLEN;

    const int g1 = u;
    const int g2 = u + SJ_HALF;
    const bool has2 = (g2 < SJ_GROUPS);
    const int c1 = g1 * 8;
    const int c2 = g2 * 8;

    // Front-batch independent streaming loads for MLP.
    const float4 x0a = __ldcs(reinterpret_cast<const float4*>(xr + c1));
    const float4 x1a = __ldcs(reinterpret_cast<const float4*>(xr + c1 + 4));
    float4 x0b, x1b;
    if (has2) {
        x0b = __ldcs(reinterpret_cast<const float4*>(xr + c2));
        x1b = __ldcs(reinterpret_cast<const float4*>(xr + c2 + 4));
    }

    const float A1 = sj_dispatchA(xr, ys, c1);

    float4 z0, z1;
    z0.x = fmaf(A1, ya.x, x0a.x);
    z0.y = fmaf(A1, ya.y, x0a.y);
    z0.z = fmaf(A1, ya.z, x0a.z);
    z0.w = fmaf(A1, ya.w, x0a.w);
    z1.x = fmaf(A1, yb.x, x1a.x);
    z1.y = fmaf(A1, yb.y, x1a.y);
    z1.z = fmaf(A1, yb.z, x1a.z);
    z1.w = fmaf(A1, yb.w, x1a.w);
    __stcs(reinterpret_cast<float4*>(orow + c1),     z0);
    __stcs(reinterpret_cast<float4*>(orow + c1 + 4), z1);

    if (has2) {
        const float A2 = sj_dispatchA(xr, ys, c2);
        float4 w0, w1;
        w0.x = fmaf(A2, ya.x, x0b.x);
        w0.y = fmaf(A2, ya.y, x0b.y);
        w0.z = fmaf(A2, ya.z, x0b.z);
        w0.w = fmaf(A2, ya.w, x0b.w);
        w1.x = fmaf(A2, yb.x, x1b.x);
        w1.y = fmaf(A2, yb.y, x1b.y);
        w1.z = fmaf(A2, yb.z, x1b.z);
        w1.w = fmaf(A2, yb.w, x1b.w);
        __stcs(reinterpret_cast<float4*>(orow + c2),     w0);
        __stcs(reinterpret_cast<float4*>(orow + c2 + 4), w1);
    }
}

extern "C" void kernel_launch(void* const* d_in, const int* in_sizes, int n_in,
                              void* d_out, int out_size) {
    const float* x = (const float*)d_in[0];   // [128, 299592] fp32
    const float* y = (const float*)d_in[1];   // [128, 8] fp32
    float* out = (float*)d_out;

    dim3 block(256);
    dim3 grid((SJ_HALF + 255) / 256, SJ_BATCH);   // 74 x 128
    sigjoin2g_kernel<<<grid, block>>>(x, y, out);
}

// round 10
// speedup vs baseline: 1.8626x; 1.0296x over previous
#include <cuda_runtime.h>
#include <cstdint>

// SigJoin (Chen's identity), D=8, M=6, BATCH=128, SIGLEN=299592.
// z[j] = x[j] + A(j>>3) * y[j&7];  A constant per aligned 8-group.
// One thread per group (fully coalesced float4 pairs). y in registers for the
// 8 fixed-index FMAs; smem ys[] only for dynamic digit lookups in chenA.

#define SJ_D      8
#define SJ_SIGLEN 299592
#define SJ_BATCH  128
#define SJ_GROUPS (SJ_SIGLEN / 8)   // 37449 groups per row

__device__ __forceinline__ float sj_invf(int n) {
    const float t[7] = {0.f, 1.f, 0.5f, 1.f/6.f, 1.f/24.f, 1.f/120.f, 1.f/720.f};
    return t[n];
}

__device__ __forceinline__ int sj_loff(int i) {
    const int t[7] = {0, 0, 8, 72, 584, 4680, 37448};
    return t[i];
}

// A = sum_{i=0}^{K-1} X_i * P_i * invf(K-i),  P_i = prod_{t=i}^{K-2} y[d_t].
template <int K>
__device__ __forceinline__ float sj_chenA(const float* __restrict__ xr,
                                          const float* __restrict__ ys,
                                          int r) {
    float A = 0.f;
    float P = 1.f;
    int idx = r;
#pragma unroll
    for (int i = K - 1; i >= 1; --i) {
        idx >>= 3;                                   // idx = r >> 3*(K-i)
        A += __ldg(xr + sj_loff(i) + idx) * (P * sj_invf(K - i));
        P *= ys[idx & 7];                            // fold digit d_{i-1}
    }
    return A + P * sj_invf(K);                       // i=0 term (pure exp), X_0=1
}

__global__ __launch_bounds__(256) void sigjoin8r_kernel(
    const float* __restrict__ x,   // [BATCH, SIGLEN]
    const float* __restrict__ y,   // [BATCH, 8]
    float* __restrict__ out)       // [BATCH, SIGLEN]
{
    const int b = blockIdx.y;
    __shared__ float ys[8];
    if (threadIdx.x < 8) ys[threadIdx.x] = y[b * SJ_D + threadIdx.x];
    __syncthreads();

    const int g = blockIdx.x * blockDim.x + threadIdx.x;  // group index
    if (g >= SJ_GROUPS) return;
    const int c = g * 8;

    const float* xr   = x   + (size_t)b * SJ_SIGLEN;
    float*       orow = out + (size_t)b * SJ_SIGLEN;

    // Streaming bulk loads (evict-first: no reuse of level-k body).
    const float4 x0 = __ldcs(reinterpret_cast<const float4*>(xr + c));
    const float4 x1 = __ldcs(reinterpret_cast<const float4*>(xr + c + 4));

    // Register-resident y (one L1 line, broadcast across the block).
    const float4 ya = __ldg(reinterpret_cast<const float4*>(y + b * SJ_D));
    const float4 yb = __ldg(reinterpret_cast<const float4*>(y + b * SJ_D + 4));

    // Level dispatch + shared prefix accumulator A (one per 8-group).
    float A;
    if (c >= 37448)      A = sj_chenA<6>(xr, ys, c - 37448);
    else if (c >= 4680)  A = sj_chenA<5>(xr, ys, c - 4680);
    else if (c >= 584)   A = sj_chenA<4>(xr, ys, c - 584);
    else if (c >= 72)    A = sj_chenA<3>(xr, ys, c - 72);
    else if (c >= 8)     A = sj_chenA<2>(xr, ys, c - 8);
    else                 A = 1.f;                         // level 1: z = x + y

    float4 z0, z1;
    z0.x = fmaf(A, ya.x, x0.x);
    z0.y = fmaf(A, ya.y, x0.y);
    z0.z = fmaf(A, ya.z, x0.z);
    z0.w = fmaf(A, ya.w, x0.w);
    z1.x = fmaf(A, yb.x, x1.x);
    z1.y = fmaf(A, yb.y, x1.y);
    z1.z = fmaf(A, yb.z, x1.z);
    z1.w = fmaf(A, yb.w, x1.w);

    __stcs(reinterpret_cast<float4*>(orow + c),     z0);
    __stcs(reinterpret_cast<float4*>(orow + c + 4), z1);
}

extern "C" void kernel_launch(void* const* d_in, const int* in_sizes, int n_in,
                              void* d_out, int out_size) {
    const float* x = (const float*)d_in[0];   // [128, 299592] fp32
    const float* y = (const float*)d_in[1];   // [128, 8] fp32
    float* out = (float*)d_out;

    dim3 block(256);
    dim3 grid((SJ_GROUPS + 255) / 256, SJ_BATCH);   // 147 x 128
    sigjoin8r_kernel<<<grid, block>>>(x, y, out);
}